// round 13
// baseline (speedup 1.0000x reference)
#include <cuda_runtime.h>
#include <cuda_bf16.h>

// ---------------------------------------------------------------------------
// Model_2 : FC -> graph conv (threshold adjacency) -> conv1d x3 -> FC -> logsoftmax
// B=64, N=750, F=8, NF=250
// ---------------------------------------------------------------------------

#define INV_BN 0.9999950000374997f   // 1/sqrt(1 + 1e-5)
#define GN 750

typedef unsigned long long ull;

// Scratch (device globals; no dynamic allocation allowed)
__device__ float g_xcat[64 * 1000];          // concat [s(250) | g(750)] per batch
__device__ float g_pool2[64 * 64 * 250];     // after conv2+bn+relu+pool
__device__ float g_part3[250 * 64 * 128];    // conv3 K-split partials [ks][b][oc]
__device__ float g_red[16 * 64 * 128];       // stage-1 reduced partials [s][b][oc]

// ---- packed f32x2 helpers (sm_100+ : 2x fp32 FMA throughput) ----------------
__device__ __forceinline__ ull pk2(float lo, float hi) {
    ull r;
    asm("mov.b64 %0, {%1,%2};" : "=l"(r) : "f"(lo), "f"(hi));
    return r;
}
__device__ __forceinline__ ull fma2(ull a, ull b, ull c) {
    ull d;
    asm("fma.rn.f32x2 %0, %1, %2, %3;" : "=l"(d) : "l"(a), "l"(b), "l"(c));
    return d;
}
__device__ __forceinline__ float2 upk2(ull v) {
    float2 r;
    asm("mov.b64 {%0,%1}, %2;" : "=f"(r.x), "=f"(r.y) : "l"(v));
    return r;
}

// ---------------------------------------------------------------------------
// K_front: blocks 0..63 -> graph conv per batch; blocks 64..127 -> linear1.
// Graph: hybrid bitonic sort + exact interval search + prefix sums.
// (diff*diff < 0.01f) is monotone in |diff| in fp32 -> adjacency = contiguous
// interval in sorted order; identical-predicate binary search reproduces the
// exact reference edge set.
// ---------------------------------------------------------------------------
__global__ void __launch_bounds__(1024) k_front(
        const float* __restrict__ xs, const float* __restrict__ W1,
        const float* __restrict__ b1, const float* __restrict__ gl,
        const float* __restrict__ bl,
        const float* __restrict__ xg, const float* __restrict__ Wg,
        const float* __restrict__ bg, const float* __restrict__ g1,
        const float* __restrict__ be1) {
    int t = threadIdx.x;
    __shared__ float sd[1024];
    __shared__ int   si[1024];
    __shared__ float pre[751 * 8];
    __shared__ float wsum[32][8];
    __shared__ float wgs[64];
    __shared__ float part[4][256];

    if (blockIdx.x >= 64) {
        // ------- linear1 path -------
        int b = blockIdx.x - 64;
        if (t < 250) sd[t] = xs[b * 250 + t];
        __syncthreads();
        int o = t & 255, ksp = t >> 8;       // 4 k-splits x 256 outputs
        if (o < 250) {
            int kb = ksp * 63;
            int ke = (ksp == 3) ? 250 : kb + 63;
            float a0 = 0.f, a1 = 0.f, a2 = 0.f, a3 = 0.f;
            int k = kb;
            #pragma unroll 4
            for (; k + 4 <= ke; k += 4) {
                a0 = fmaf(sd[k],     W1[(k)     * 250 + o], a0);
                a1 = fmaf(sd[k + 1], W1[(k + 1) * 250 + o], a1);
                a2 = fmaf(sd[k + 2], W1[(k + 2) * 250 + o], a2);
                a3 = fmaf(sd[k + 3], W1[(k + 3) * 250 + o], a3);
            }
            for (; k < ke; k++) a0 = fmaf(sd[k], W1[k * 250 + o], a0);
            part[ksp][o] = (a0 + a1) + (a2 + a3);
        }
        __syncthreads();
        if (t < 250) {
            float acc = (part[0][t] + part[1][t]) + (part[2][t] + part[3][t]);
            float v = (acc + b1[t]) * (INV_BN * gl[t]) + bl[t];
            g_xcat[b * 1000 + t] = fmaxf(v, 0.f);
        }
        return;
    }

    // ------- graph path -------
    int b = blockIdx.x;
    float key;
    int   pay;
    if (t < GN) { key = xg[b * 6000 + t * 8]; pay = t; }
    else        { key = __int_as_float(0x7f800000); pay = -1; }
    if (t < 64) wgs[t] = Wg[t];

    // hybrid bitonic sort ascending, 1 element per thread
    for (int k2 = 2; k2 <= 1024; k2 <<= 1) {
        bool up = ((t & k2) == 0);
        for (int j = k2 >> 1; j > 0; j >>= 1) {
            float kq; int pq;
            if (j >= 32) {
                __syncthreads();
                sd[t] = key; si[t] = pay;
                __syncthreads();
                kq = sd[t ^ j]; pq = si[t ^ j];
            } else {
                kq = __shfl_xor_sync(0xffffffffu, key, j);
                pq = __shfl_xor_sync(0xffffffffu, pay, j);
            }
            bool lower = (t & j) == 0;
            float a = lower ? key : kq;
            float c = lower ? kq : key;
            bool sw = up ? (a > c) : (a < c);
            if (sw) { key = kq; pay = pq; }
        }
    }
    __syncthreads();
    sd[t] = key; si[t] = pay;
    __syncthreads();

    float dn = 0.f;
    int lo = 0, hi = 0;
    float y[8];
    if (t < GN) {
        float dsv = key;
        int L = 0, R = t;
        while (L < R) { int m = (L + R) >> 1; float df = dsv - sd[m];
                        if (df * df < 0.01f) R = m; else L = m + 1; }
        lo = L;
        L = t + 1; R = GN;
        while (L < R) { int m = (L + R) >> 1; float df = dsv - sd[m];
                        if (df * df < 0.01f) L = m + 1; else R = m; }
        hi = L;
        dn = rsqrtf((float)(hi - lo));
        int orig = pay;
        const float4* xp = reinterpret_cast<const float4*>(xg + (size_t)b * 6000 + orig * 8);
        float4 a4 = xp[0], c4 = xp[1];
        float xv[8] = {a4.x, a4.y, a4.z, a4.w, c4.x, c4.y, c4.z, c4.w};
        #pragma unroll
        for (int f = 0; f < 8; f++) {
            float s = 0.f;
            #pragma unroll
            for (int fp = 0; fp < 8; fp++) s = fmaf(xv[fp], wgs[fp * 8 + f], s);
            y[f] = s * dn;
        }
    } else {
        #pragma unroll
        for (int f = 0; f < 8; f++) y[f] = 0.f;
    }

    int lane = t & 31, wrp = t >> 5;
    #pragma unroll
    for (int f = 0; f < 8; f++) {
        float v = y[f];
        #pragma unroll
        for (int d = 1; d < 32; d <<= 1) {
            float o = __shfl_up_sync(0xffffffffu, v, d);
            if (lane >= d) v += o;
        }
        y[f] = v;
    }
    if (lane == 31) {
        #pragma unroll
        for (int f = 0; f < 8; f++) wsum[wrp][f] = y[f];
    }
    __syncthreads();
    if (t < 8) {
        float run = 0.f;
        for (int w = 0; w < 32; w++) { float x = wsum[w][t]; wsum[w][t] = run; run += x; }
    }
    __syncthreads();
    if (t < GN) {
        #pragma unroll
        for (int f = 0; f < 8; f++) pre[(t + 1) * 8 + f] = y[f] + wsum[wrp][f];
    }
    if (t < 8) pre[t] = 0.f;
    __syncthreads();

    if (t < GN) {
        float sc = INV_BN * g1[0], sh = be1[0];
        float gsum = 0.f;
        #pragma unroll
        for (int f = 0; f < 8; f++) {
            float s = pre[hi * 8 + f] - pre[lo * 8 + f];
            float hv = fmaf(dn, s, bg[f]);
            hv = fmaf(hv, sc, sh);
            gsum += fmaxf(hv, 0.f);
        }
        g_xcat[b * 1000 + 250 + pay] = gsum * 0.125f;
    }
}

// ---------------------------------------------------------------------------
// K_conv12: FUSED conv1+pool1+conv2+pool2.
// Each block (b, pt, oh) recomputes its own pool1 slab from g_xcat (exactly
// the reference conv1 arithmetic), then runs the conv2 f32x2 mainloop.
// grid (64, 4, 2), 64 threads.
// ---------------------------------------------------------------------------
__global__ void __launch_bounds__(64) k_conv12(
        const float* __restrict__ Wc1, const float* __restrict__ bc1,
        const float* __restrict__ gc1, const float* __restrict__ bec1,
        const float* __restrict__ Wc2, const float* __restrict__ bc2,
        const float* __restrict__ gc2, const float* __restrict__ bec2) {
    int b = blockIdx.x, pt = blockIdx.y, oh = blockIdx.z;
    int p0 = pt * 64;            // pooled(2) start
    int oc0 = oh * 32;
    __shared__ float swt[160][33];                 // conv2 w: [ic*5+k][oc_local]
    __shared__ __align__(16) float2 sxe[8][66];    // conv2 input pairs (even phase)
    __shared__ __align__(16) float2 sxo[8][66];    // (odd phase)
    __shared__ float pool1s[8][134];               // pool1 slab for 8-ic chunk
    __shared__ float xsl[272];                     // xcat slab
    __shared__ float w1[160], b1s[32], g1s[32], e1s[32];
    int t = threadIdx.x;
    int ocg = t & 7;             // oc_local base = 4*ocg
    int pg  = t >> 3;            // pooled base j0 = 8*pg (0..7)

    // xcat slab: covers xcat idx [4p0-6, 4p0+265], zeros outside [0,1000)
    int xbase = 4 * p0 - 6;
    for (int i = t; i < 272; i += 64) {
        int gi = xbase + i;
        xsl[i] = (gi >= 0 && gi < 1000) ? g_xcat[b * 1000 + gi] : 0.f;
    }
    for (int i = t; i < 160; i += 64) w1[i] = Wc1[i];
    if (t < 32) { b1s[t] = bc1[t]; g1s[t] = gc1[t] * INV_BN; e1s[t] = bec1[t]; }

    // staged vectorized conv2 weight load: 32 oc x 160 = 1280 float4
    {
        float4 rw[20];
        #pragma unroll
        for (int j = 0; j < 20; j++) {
            int i4 = t + j * 64;
            int o = i4 / 40, r = i4 - o * 40;
            rw[j] = *reinterpret_cast<const float4*>(Wc2 + (oc0 + o) * 160 + 4 * r);
        }
        #pragma unroll
        for (int j = 0; j < 20; j++) {
            int i4 = t + j * 64;
            int o = i4 / 40, r = i4 - o * 40;
            swt[4 * r + 0][o] = rw[j].x;
            swt[4 * r + 1][o] = rw[j].y;
            swt[4 * r + 2][o] = rw[j].z;
            swt[4 * r + 3][o] = rw[j].w;
        }
    }

    ull acc[4][8];
    #pragma unroll
    for (int oo = 0; oo < 4; oo++)
        #pragma unroll
        for (int j = 0; j < 8; j++) acc[oo][j] = 0ull;

    int qb = 2 * p0 - 2;          // pool1 slab origin (global pool1 position)

    for (int c = 0; c < 4; c++) {           // ic chunks of 8
        __syncthreads();
        // ---- conv1 + bn + relu + maxpool into pool1s (exact ref arithmetic) ----
        for (int i = t; i < 8 * 133; i += 64) {
            int ic = i / 133, m = i - ic * 133;   // m = q - qb
            int q = qb + m;
            float P = 0.f;
            if (q >= 0 && q < 500) {
                int icg = 8 * c + ic;
                const float* wr = &w1[icg * 5];
                float v0 = b1s[icg], v1 = v0;
                #pragma unroll
                for (int k = 0; k < 5; k++) {
                    float wk = wr[k];
                    v0 = fmaf(xsl[2 * m + k],     wk, v0);
                    v1 = fmaf(xsl[2 * m + 1 + k], wk, v1);
                }
                v0 = fmaf(v0, g1s[icg], e1s[icg]);
                v1 = fmaf(v1, g1s[icg], e1s[icg]);
                P = fmaxf(fmaxf(v0, v1), 0.f);
            }
            pool1s[ic][m] = P;
        }
        __syncthreads();
        // ---- build even/odd phase pair arrays ----
        for (int i = t; i < 8 * 66; i += 64) {
            int ic = i / 66, j = i - ic * 66;
            sxe[ic][j] = make_float2(pool1s[ic][2 * j],     pool1s[ic][2 * j + 1]);
            sxo[ic][j] = make_float2(pool1s[ic][2 * j + 1], pool1s[ic][2 * j + 2]);
        }
        __syncthreads();
        // ---- conv2 f32x2 mainloop ----
        #pragma unroll 2
        for (int i8 = 0; i8 < 8; i8++) {
            int ic = c * 8 + i8;
            ull e[10], o[10];
            const ulonglong2* ep = reinterpret_cast<const ulonglong2*>(&sxe[i8][8 * pg]);
            const ulonglong2* op = reinterpret_cast<const ulonglong2*>(&sxo[i8][8 * pg]);
            #pragma unroll
            for (int q = 0; q < 5; q++) {
                ulonglong2 ve = ep[q]; e[2 * q] = ve.x; e[2 * q + 1] = ve.y;
                ulonglong2 vo = op[q]; o[2 * q] = vo.x; o[2 * q + 1] = vo.y;
            }
            #pragma unroll
            for (int oo = 0; oo < 4; oo++) {
                int ol = 4 * ocg + oo;
                float w0 = swt[ic * 5 + 0][ol];
                float w1v = swt[ic * 5 + 1][ol];
                float w2 = swt[ic * 5 + 2][ol];
                float w3 = swt[ic * 5 + 3][ol];
                float w4 = swt[ic * 5 + 4][ol];
                ull wd0 = pk2(w0, w0), wd1 = pk2(w1v, w1v), wd2 = pk2(w2, w2);
                ull wd3 = pk2(w3, w3), wd4 = pk2(w4, w4);
                #pragma unroll
                for (int j = 0; j < 8; j++) {
                    ull a = acc[oo][j];
                    a = fma2(e[j],     wd0, a);
                    a = fma2(o[j],     wd1, a);
                    a = fma2(e[j + 1], wd2, a);
                    a = fma2(o[j + 1], wd3, a);
                    a = fma2(e[j + 2], wd4, a);
                    acc[oo][j] = a;
                }
            }
        }
    }

    #pragma unroll
    for (int oo = 0; oo < 4; oo++) {
        int oc = oc0 + 4 * ocg + oo;
        float bb = bc2[oc];
        float gg = gc2[oc] * INV_BN;
        float be = bec2[oc];
        #pragma unroll
        for (int j = 0; j < 8; j++) {
            float2 a = upk2(acc[oo][j]);
            float r = fmaxf(fmaxf(fmaf(a.x + bb, gg, be), fmaf(a.y + bb, gg, be)), 0.f);
            int p = p0 + 8 * pg + j;
            if (p < 250) g_pool2[(b * 64 + oc) * 250 + p] = r;
        }
    }
}

// ---------------------------------------------------------------------------
// K5: conv3 K-split GEMM, K=64 chunks: grid 250, 512 threads (16 warps).
// Staged vector loads (W 4 + X 2 LDG.128/thread, ALL before any STS).
// f32x2 lanes = adjacent batch pair; thread tile 4 b x 4 oc, oc strided 32.
// ---------------------------------------------------------------------------
__global__ void __launch_bounds__(512) k_conv3(const float* __restrict__ Wc3) {
    int ks = blockIdx.x;       // 0..249
    int t = threadIdx.x;
    __shared__ __align__(16) float Xs[64][68];   // [kk][b], pad 68 (16B-aligned rows)
    __shared__ float Ws[64][133];                // [kk][oc], pad 133 (conflict-free)
    int k0 = ks * 64;

    // ---- staged vector loads: ALL LDG.128 first, then all STS ----
    float4 rw[4], rx[2];
    #pragma unroll
    for (int j = 0; j < 4; j++) {
        int i4 = t + j * 512;            // 0..2047 -> 128 oc x 16 float4
        int oc = i4 >> 4, kq = i4 & 15;
        rw[j] = *reinterpret_cast<const float4*>(Wc3 + oc * 16000 + k0 + 4 * kq);
    }
    #pragma unroll
    for (int j = 0; j < 2; j++) {
        int i4 = t + j * 512;            // 0..1023 -> 64 b x 16 float4
        int bb = i4 >> 4, kq = i4 & 15;
        rx[j] = *reinterpret_cast<const float4*>(g_pool2 + bb * 16000 + k0 + 4 * kq);
    }
    #pragma unroll
    for (int j = 0; j < 4; j++) {
        int i4 = t + j * 512;
        int oc = i4 >> 4, kq = i4 & 15;
        Ws[4 * kq + 0][oc] = rw[j].x;
        Ws[4 * kq + 1][oc] = rw[j].y;
        Ws[4 * kq + 2][oc] = rw[j].z;
        Ws[4 * kq + 3][oc] = rw[j].w;
    }
    #pragma unroll
    for (int j = 0; j < 2; j++) {
        int i4 = t + j * 512;
        int bb = i4 >> 4, kq = i4 & 15;
        Xs[4 * kq + 0][bb] = rx[j].x;
        Xs[4 * kq + 1][bb] = rx[j].y;
        Xs[4 * kq + 2][bb] = rx[j].z;
        Xs[4 * kq + 3][bb] = rx[j].w;
    }
    __syncthreads();

    int og = t & 31;           // oc = og + 32*o, o=0..3
    int bg = t >> 5;           // warp id 0..15 -> b0 = 4*bg (x loads warp-broadcast)

    ull acc[4][2];
    #pragma unroll
    for (int o = 0; o < 4; o++) { acc[o][0] = 0ull; acc[o][1] = 0ull; }

    #pragma unroll 8
    for (int kk = 0; kk < 64; kk++) {
        const ull* xq = reinterpret_cast<const ull*>(&Xs[kk][4 * bg]);
        ull x0 = xq[0], x1 = xq[1];
        #pragma unroll
        for (int o = 0; o < 4; o++) {
            float wv = Ws[kk][og + 32 * o];
            ull wd = pk2(wv, wv);
            acc[o][0] = fma2(x0, wd, acc[o][0]);
            acc[o][1] = fma2(x1, wd, acc[o][1]);
        }
    }

    #pragma unroll
    for (int o = 0; o < 4; o++) {
        int oc = og + 32 * o;
        #pragma unroll
        for (int j = 0; j < 2; j++) {
            float2 v = upk2(acc[o][j]);
            int bb = 4 * bg + 2 * j;
            g_part3[(ks * 64 + bb) * 128 + oc]     = v.x;
            g_part3[(ks * 64 + bb + 1) * 128 + oc] = v.y;
        }
    }
}

// ---------------------------------------------------------------------------
// K_red: stage-1 partial reduction. grid (8 slice-pairs, 64 b), 256 threads.
// Thread (oc, h): slice s = 2*rc+h sums ks = s, s+16, s+32, ... with 4
// independent accumulators (MLP >= 4). Writes g_red[s][b][oc].
// ---------------------------------------------------------------------------
__global__ void __launch_bounds__(256) k_red() {
    int rc = blockIdx.x;        // 0..7
    int b  = blockIdx.y;        // 0..63
    int t  = threadIdx.x;
    int oc = t & 127, h = t >> 7;
    int s = rc * 2 + h;         // slice 0..15
    const float* p = g_part3 + b * 128 + oc;
    float a0 = 0.f, a1 = 0.f, a2 = 0.f, a3 = 0.f;
    int ks = s;
    for (; ks + 48 < 250; ks += 64) {
        float v0 = p[(size_t)(ks)      * 8192];
        float v1 = p[(size_t)(ks + 16) * 8192];
        float v2 = p[(size_t)(ks + 32) * 8192];
        float v3 = p[(size_t)(ks + 48) * 8192];
        a0 += v0; a1 += v1; a2 += v2; a3 += v3;
    }
    for (; ks < 250; ks += 16) a0 += p[(size_t)ks * 8192];
    g_red[(s * 64 + b) * 128 + oc] = (a0 + a1) + (a2 + a3);
}

// ---------------------------------------------------------------------------
// K6: final reduce (+bc3), FC 128->64 (+bn relu), FC 64->12, log_softmax.
// one block per batch, 128 threads; 16 partial loads per thread, 4-batched.
// ---------------------------------------------------------------------------
__global__ void __launch_bounds__(128) k_fc(
        const float* __restrict__ bc3, const float* __restrict__ Wf,
        const float* __restrict__ bf, const float* __restrict__ gf,
        const float* __restrict__ bef, const float* __restrict__ Wo,
        const float* __restrict__ bo, float* __restrict__ out) {
    int b = blockIdx.x;
    int t = threadIdx.x;
    __shared__ float f[128], u[64], o[12];
    {
        const float* p = g_red + b * 128 + t;
        float a0 = 0.f, a1 = 0.f, a2 = 0.f, a3 = 0.f;
        #pragma unroll
        for (int s = 0; s < 16; s += 4) {
            a0 += p[(s + 0) * 8192];
            a1 += p[(s + 1) * 8192];
            a2 += p[(s + 2) * 8192];
            a3 += p[(s + 3) * 8192];
        }
        f[t] = bc3[t] + ((a0 + a1) + (a2 + a3));
    }
    __syncthreads();
    if (t < 64) {
        float z = bf[t];
        #pragma unroll 8
        for (int k = 0; k < 128; k++) z = fmaf(f[k], Wf[k * 64 + t], z);
        z = z * (INV_BN * gf[t]) + bef[t];
        u[t] = fmaxf(z, 0.f);
    }
    __syncthreads();
    if (t < 12) {
        float z = bo[t];
        #pragma unroll 8
        for (int k = 0; k < 64; k++) z = fmaf(u[k], Wo[k * 12 + t], z);
        o[t] = z;
    }
    __syncthreads();
    if (t < 12) {
        float m = o[0];
        #pragma unroll
        for (int i = 1; i < 12; i++) m = fmaxf(m, o[i]);
        float s = 0.f;
        #pragma unroll
        for (int i = 0; i < 12; i++) s += expf(o[i] - m);
        out[b * 12 + t] = (o[t] - m) - logf(s);
    }
}

// ---------------------------------------------------------------------------
extern "C" void kernel_launch(void* const* d_in, const int* in_sizes, int n_in,
                              void* d_out, int out_size) {
    const float* x_sample = (const float*)d_in[0];
    const float* x_graph  = (const float*)d_in[1];
    const float* W1   = (const float*)d_in[2];
    const float* b1   = (const float*)d_in[3];
    const float* gl   = (const float*)d_in[4];
    const float* bl   = (const float*)d_in[5];
    const float* Wg   = (const float*)d_in[6];
    const float* bg   = (const float*)d_in[7];
    const float* g1   = (const float*)d_in[8];
    const float* be1  = (const float*)d_in[9];
    const float* Wc1  = (const float*)d_in[10];
    const float* bc1  = (const float*)d_in[11];
    const float* gc1  = (const float*)d_in[12];
    const float* bec1 = (const float*)d_in[13];
    const float* Wc2  = (const float*)d_in[14];
    const float* bc2  = (const float*)d_in[15];
    const float* gc2  = (const float*)d_in[16];
    const float* bec2 = (const float*)d_in[17];
    const float* Wc3  = (const float*)d_in[18];
    const float* bc3  = (const float*)d_in[19];
    const float* Wf   = (const float*)d_in[20];
    const float* bf   = (const float*)d_in[21];
    const float* gf   = (const float*)d_in[22];
    const float* bef  = (const float*)d_in[23];
    const float* Wo   = (const float*)d_in[24];
    const float* bo   = (const float*)d_in[25];
    float* out = (float*)d_out;

    k_front <<<128, 1024>>>(x_sample, W1, b1, gl, bl, x_graph, Wg, bg, g1, be1);
    k_conv12<<<dim3(64, 4, 2), 64>>>(Wc1, bc1, gc1, bec1, Wc2, bc2, gc2, bec2);
    k_conv3 <<<250, 512>>>(Wc3);
    k_red   <<<dim3(8, 64), 256>>>();
    k_fc    <<<64, 128>>>(bc3, Wf, bf, gf, bef, Wo, bo, out);
}

// round 14
// speedup vs baseline: 1.0667x; 1.0667x over previous
#include <cuda_runtime.h>
#include <cuda_bf16.h>

// ---------------------------------------------------------------------------
// Model_2 : FC -> graph conv (threshold adjacency) -> conv1d x3 -> FC -> logsoftmax
// B=64, N=750, F=8, NF=250
// ---------------------------------------------------------------------------

#define INV_BN 0.9999950000374997f   // 1/sqrt(1 + 1e-5)
#define GN 750

typedef unsigned long long ull;

// Scratch (device globals; no dynamic allocation allowed)
__device__ float g_xcat[64 * 1000];          // concat [s(250) | g(750)] per batch
__device__ float g_pool2[64 * 64 * 250];     // after conv2+bn+relu+pool
__device__ float g_part3[500 * 64 * 128];    // conv3 K-split partials [ks][b][oc]
__device__ float g_red[32 * 64 * 128];       // stage-1 reduced partials [s][b][oc]

// ---- packed f32x2 helpers (sm_100+ : 2x fp32 FMA throughput) ----------------
__device__ __forceinline__ ull pk2(float lo, float hi) {
    ull r;
    asm("mov.b64 %0, {%1,%2};" : "=l"(r) : "f"(lo), "f"(hi));
    return r;
}
__device__ __forceinline__ ull fma2(ull a, ull b, ull c) {
    ull d;
    asm("fma.rn.f32x2 %0, %1, %2, %3;" : "=l"(d) : "l"(a), "l"(b), "l"(c));
    return d;
}
__device__ __forceinline__ float2 upk2(ull v) {
    float2 r;
    asm("mov.b64 {%0,%1}, %2;" : "=f"(r.x), "=f"(r.y) : "l"(v));
    return r;
}

// ---------------------------------------------------------------------------
// K_front: blocks 0..63 -> graph conv per batch; blocks 64..127 -> linear1.
// Graph: hybrid bitonic sort + exact interval search + prefix sums.
// (diff*diff < 0.01f) is monotone in |diff| in fp32 -> adjacency = contiguous
// interval in sorted order; identical-predicate binary search reproduces the
// exact reference edge set.
// ---------------------------------------------------------------------------
__global__ void __launch_bounds__(1024) k_front(
        const float* __restrict__ xs, const float* __restrict__ W1,
        const float* __restrict__ b1, const float* __restrict__ gl,
        const float* __restrict__ bl,
        const float* __restrict__ xg, const float* __restrict__ Wg,
        const float* __restrict__ bg, const float* __restrict__ g1,
        const float* __restrict__ be1) {
    int t = threadIdx.x;
    __shared__ float sd[1024];
    __shared__ int   si[1024];
    __shared__ float pre[751 * 8];
    __shared__ float wsum[32][8];
    __shared__ float wgs[64];
    __shared__ float part[4][256];

    if (blockIdx.x >= 64) {
        // ------- linear1 path -------
        int b = blockIdx.x - 64;
        if (t < 250) sd[t] = xs[b * 250 + t];
        __syncthreads();
        int o = t & 255, ksp = t >> 8;       // 4 k-splits x 256 outputs
        if (o < 250) {
            int kb = ksp * 63;
            int ke = (ksp == 3) ? 250 : kb + 63;
            float a0 = 0.f, a1 = 0.f, a2 = 0.f, a3 = 0.f;
            int k = kb;
            #pragma unroll 4
            for (; k + 4 <= ke; k += 4) {
                a0 = fmaf(sd[k],     W1[(k)     * 250 + o], a0);
                a1 = fmaf(sd[k + 1], W1[(k + 1) * 250 + o], a1);
                a2 = fmaf(sd[k + 2], W1[(k + 2) * 250 + o], a2);
                a3 = fmaf(sd[k + 3], W1[(k + 3) * 250 + o], a3);
            }
            for (; k < ke; k++) a0 = fmaf(sd[k], W1[k * 250 + o], a0);
            part[ksp][o] = (a0 + a1) + (a2 + a3);
        }
        __syncthreads();
        if (t < 250) {
            float acc = (part[0][t] + part[1][t]) + (part[2][t] + part[3][t]);
            float v = (acc + b1[t]) * (INV_BN * gl[t]) + bl[t];
            g_xcat[b * 1000 + t] = fmaxf(v, 0.f);
        }
        return;
    }

    // ------- graph path -------
    int b = blockIdx.x;
    float key;
    int   pay;
    if (t < GN) { key = xg[b * 6000 + t * 8]; pay = t; }
    else        { key = __int_as_float(0x7f800000); pay = -1; }
    if (t < 64) wgs[t] = Wg[t];

    // hybrid bitonic sort ascending, 1 element per thread
    for (int k2 = 2; k2 <= 1024; k2 <<= 1) {
        bool up = ((t & k2) == 0);
        for (int j = k2 >> 1; j > 0; j >>= 1) {
            float kq; int pq;
            if (j >= 32) {
                __syncthreads();
                sd[t] = key; si[t] = pay;
                __syncthreads();
                kq = sd[t ^ j]; pq = si[t ^ j];
            } else {
                kq = __shfl_xor_sync(0xffffffffu, key, j);
                pq = __shfl_xor_sync(0xffffffffu, pay, j);
            }
            bool lower = (t & j) == 0;
            float a = lower ? key : kq;
            float c = lower ? kq : key;
            bool sw = up ? (a > c) : (a < c);
            if (sw) { key = kq; pay = pq; }
        }
    }
    __syncthreads();
    sd[t] = key; si[t] = pay;
    __syncthreads();

    float dn = 0.f;
    int lo = 0, hi = 0;
    float y[8];
    if (t < GN) {
        float dsv = key;
        int L = 0, R = t;
        while (L < R) { int m = (L + R) >> 1; float df = dsv - sd[m];
                        if (df * df < 0.01f) R = m; else L = m + 1; }
        lo = L;
        L = t + 1; R = GN;
        while (L < R) { int m = (L + R) >> 1; float df = dsv - sd[m];
                        if (df * df < 0.01f) L = m + 1; else R = m; }
        hi = L;
        dn = rsqrtf((float)(hi - lo));
        int orig = pay;
        const float4* xp = reinterpret_cast<const float4*>(xg + (size_t)b * 6000 + orig * 8);
        float4 a4 = xp[0], c4 = xp[1];
        float xv[8] = {a4.x, a4.y, a4.z, a4.w, c4.x, c4.y, c4.z, c4.w};
        #pragma unroll
        for (int f = 0; f < 8; f++) {
            float s = 0.f;
            #pragma unroll
            for (int fp = 0; fp < 8; fp++) s = fmaf(xv[fp], wgs[fp * 8 + f], s);
            y[f] = s * dn;
        }
    } else {
        #pragma unroll
        for (int f = 0; f < 8; f++) y[f] = 0.f;
    }

    int lane = t & 31, wrp = t >> 5;
    #pragma unroll
    for (int f = 0; f < 8; f++) {
        float v = y[f];
        #pragma unroll
        for (int d = 1; d < 32; d <<= 1) {
            float o = __shfl_up_sync(0xffffffffu, v, d);
            if (lane >= d) v += o;
        }
        y[f] = v;
    }
    if (lane == 31) {
        #pragma unroll
        for (int f = 0; f < 8; f++) wsum[wrp][f] = y[f];
    }
    __syncthreads();
    if (t < 8) {
        float run = 0.f;
        for (int w = 0; w < 32; w++) { float x = wsum[w][t]; wsum[w][t] = run; run += x; }
    }
    __syncthreads();
    if (t < GN) {
        #pragma unroll
        for (int f = 0; f < 8; f++) pre[(t + 1) * 8 + f] = y[f] + wsum[wrp][f];
    }
    if (t < 8) pre[t] = 0.f;
    __syncthreads();

    if (t < GN) {
        float sc = INV_BN * g1[0], sh = be1[0];
        float gsum = 0.f;
        #pragma unroll
        for (int f = 0; f < 8; f++) {
            float s = pre[hi * 8 + f] - pre[lo * 8 + f];
            float hv = fmaf(dn, s, bg[f]);
            hv = fmaf(hv, sc, sh);
            gsum += fmaxf(hv, 0.f);
        }
        g_xcat[b * 1000 + 250 + pay] = gsum * 0.125f;
    }
}

// ---------------------------------------------------------------------------
// K_conv12: FUSED conv1+pool1+conv2+pool2. Pooled tile 32 -> grid (64,8,2),
// 1024 blocks (~14 warps/SM) for latency hiding. Each block recomputes its
// pool1 slab from g_xcat (exact reference conv1 arithmetic), then runs the
// conv2 f32x2 mainloop. 64 threads: thread = 4 oc x 4 pooled.
// ---------------------------------------------------------------------------
__global__ void __launch_bounds__(64) k_conv12(
        const float* __restrict__ Wc1, const float* __restrict__ bc1,
        const float* __restrict__ gc1, const float* __restrict__ bec1,
        const float* __restrict__ Wc2, const float* __restrict__ bc2,
        const float* __restrict__ gc2, const float* __restrict__ bec2) {
    int b = blockIdx.x, pt = blockIdx.y, oh = blockIdx.z;
    int p0 = pt * 32;            // pooled(2) start
    int oc0 = oh * 32;
    __shared__ float swt[160][33];                 // conv2 w: [ic*5+k][oc_local]
    __shared__ __align__(16) float2 sxe[8][34];    // conv2 input pairs (even phase)
    __shared__ __align__(16) float2 sxo[8][34];    // (odd phase)
    __shared__ float pool1s[8][69];                // pool1 slab for 8-ic chunk
    __shared__ float xsl[152];                     // xcat slab
    __shared__ float w1[160], b1s[32], g1s[32], e1s[32];
    int t = threadIdx.x;
    int ocg = t & 7;             // oc_local base = 4*ocg
    int pg  = t >> 3;            // pooled base j0 = 4*pg (0..7)

    // xcat slab: covers xcat idx [4p0-6, 4p0+139], zeros outside [0,1000)
    int xbase = 4 * p0 - 6;
    for (int i = t; i < 146; i += 64) {
        int gi = xbase + i;
        xsl[i] = (gi >= 0 && gi < 1000) ? g_xcat[b * 1000 + gi] : 0.f;
    }
    for (int i = t; i < 160; i += 64) w1[i] = Wc1[i];
    if (t < 32) { b1s[t] = bc1[t]; g1s[t] = gc1[t] * INV_BN; e1s[t] = bec1[t]; }

    // staged vectorized conv2 weight load: 32 oc x 160 = 1280 float4
    {
        float4 rw[20];
        #pragma unroll
        for (int j = 0; j < 20; j++) {
            int i4 = t + j * 64;
            int o = i4 / 40, r = i4 - o * 40;
            rw[j] = *reinterpret_cast<const float4*>(Wc2 + (oc0 + o) * 160 + 4 * r);
        }
        #pragma unroll
        for (int j = 0; j < 20; j++) {
            int i4 = t + j * 64;
            int o = i4 / 40, r = i4 - o * 40;
            swt[4 * r + 0][o] = rw[j].x;
            swt[4 * r + 1][o] = rw[j].y;
            swt[4 * r + 2][o] = rw[j].z;
            swt[4 * r + 3][o] = rw[j].w;
        }
    }

    ull acc[4][4];
    #pragma unroll
    for (int oo = 0; oo < 4; oo++)
        #pragma unroll
        for (int j = 0; j < 4; j++) acc[oo][j] = 0ull;

    int qb = 2 * p0 - 2;          // pool1 slab origin (global pool1 position)

    for (int c = 0; c < 4; c++) {           // ic chunks of 8
        __syncthreads();
        // ---- conv1 + bn + relu + maxpool into pool1s (exact ref arithmetic) ----
        for (int i = t; i < 8 * 69; i += 64) {
            int ic = i / 69, m = i - ic * 69;   // m = q - qb
            int q = qb + m;
            float P = 0.f;
            if (q >= 0 && q < 500) {
                int icg = 8 * c + ic;
                const float* wr = &w1[icg * 5];
                float v0 = b1s[icg], v1 = v0;
                #pragma unroll
                for (int k = 0; k < 5; k++) {
                    float wk = wr[k];
                    v0 = fmaf(xsl[2 * m + k],     wk, v0);
                    v1 = fmaf(xsl[2 * m + 1 + k], wk, v1);
                }
                v0 = fmaf(v0, g1s[icg], e1s[icg]);
                v1 = fmaf(v1, g1s[icg], e1s[icg]);
                P = fmaxf(fmaxf(v0, v1), 0.f);
            }
            pool1s[ic][m] = P;
        }
        __syncthreads();
        // ---- build even/odd phase pair arrays ----
        for (int i = t; i < 8 * 34; i += 64) {
            int ic = i / 34, j = i - ic * 34;
            sxe[ic][j] = make_float2(pool1s[ic][2 * j],     pool1s[ic][2 * j + 1]);
            sxo[ic][j] = make_float2(pool1s[ic][2 * j + 1], pool1s[ic][2 * j + 2]);
        }
        __syncthreads();
        // ---- conv2 f32x2 mainloop ----
        #pragma unroll 2
        for (int i8 = 0; i8 < 8; i8++) {
            int ic = c * 8 + i8;
            const ulonglong2* ep = reinterpret_cast<const ulonglong2*>(&sxe[i8][4 * pg]);
            const ulonglong2* op = reinterpret_cast<const ulonglong2*>(&sxo[i8][4 * pg]);
            ulonglong2 q0 = ep[0], q1 = ep[1], q2 = ep[2];
            ull e0 = q0.x, e1 = q0.y, e2 = q1.x, e3 = q1.y, e4 = q2.x, e5 = q2.y;
            ulonglong2 r0 = op[0], r1 = op[1], r2 = op[2];
            ull o0 = r0.x, o1 = r0.y, o2 = r1.x, o3 = r1.y, o4 = r2.x;
            #pragma unroll
            for (int oo = 0; oo < 4; oo++) {
                int ol = 4 * ocg + oo;
                float w0 = swt[ic * 5 + 0][ol];
                float w1v = swt[ic * 5 + 1][ol];
                float w2 = swt[ic * 5 + 2][ol];
                float w3 = swt[ic * 5 + 3][ol];
                float w4 = swt[ic * 5 + 4][ol];
                ull wd0 = pk2(w0, w0), wd1 = pk2(w1v, w1v), wd2 = pk2(w2, w2);
                ull wd3 = pk2(w3, w3), wd4 = pk2(w4, w4);
                ull a;
                a = acc[oo][0];
                a = fma2(e0, wd0, a); a = fma2(o0, wd1, a); a = fma2(e1, wd2, a);
                a = fma2(o1, wd3, a); a = fma2(e2, wd4, a);
                acc[oo][0] = a;
                a = acc[oo][1];
                a = fma2(e1, wd0, a); a = fma2(o1, wd1, a); a = fma2(e2, wd2, a);
                a = fma2(o2, wd3, a); a = fma2(e3, wd4, a);
                acc[oo][1] = a;
                a = acc[oo][2];
                a = fma2(e2, wd0, a); a = fma2(o2, wd1, a); a = fma2(e3, wd2, a);
                a = fma2(o3, wd3, a); a = fma2(e4, wd4, a);
                acc[oo][2] = a;
                a = acc[oo][3];
                a = fma2(e3, wd0, a); a = fma2(o3, wd1, a); a = fma2(e4, wd2, a);
                a = fma2(o4, wd3, a); a = fma2(e5, wd4, a);
                acc[oo][3] = a;
            }
        }
    }

    #pragma unroll
    for (int oo = 0; oo < 4; oo++) {
        int oc = oc0 + 4 * ocg + oo;
        float bb = bc2[oc];
        float gg = gc2[oc] * INV_BN;
        float be = bec2[oc];
        #pragma unroll
        for (int j = 0; j < 4; j++) {
            float2 a = upk2(acc[oo][j]);
            float r = fmaxf(fmaxf(fmaf(a.x + bb, gg, be), fmaf(a.y + bb, gg, be)), 0.f);
            int p = p0 + 4 * pg + j;
            if (p < 250) g_pool2[(b * 64 + oc) * 250 + p] = r;
        }
    }
}

// ---------------------------------------------------------------------------
// K5: conv3 K-split GEMM (proven best config): grid 500 (32-k chunks), 256 thr.
// Staged vector loads (W 4 + X 2 LDG.128/thread, ALL before any STS).
// f32x2 lanes = adjacent batch pair; thread tile 8 b x 4 oc, oc strided 32.
// ---------------------------------------------------------------------------
__global__ void __launch_bounds__(256) k_conv3(const float* __restrict__ Wc3) {
    int ks = blockIdx.x;       // 0..499
    int t = threadIdx.x;
    __shared__ __align__(16) float Xs[32][68];   // [kk][b], pad 68
    __shared__ float Ws[32][133];                // [kk][oc], pad 133 (conflict-free)
    int og = t & 31;           // oc = og + 32*o, o=0..3
    int bg = t >> 5;           // warp id -> b0 = 8*bg (x loads warp-broadcast)
    int k0 = ks * 32;

    float4 rw[4], rx[2];
    #pragma unroll
    for (int j = 0; j < 4; j++) {
        int i4 = t + j * 256;
        int oc = i4 >> 3, kq = i4 & 7;
        rw[j] = *reinterpret_cast<const float4*>(Wc3 + oc * 16000 + k0 + 4 * kq);
    }
    #pragma unroll
    for (int j = 0; j < 2; j++) {
        int i4 = t + j * 256;
        int bb = i4 >> 3, kq = i4 & 7;
        rx[j] = *reinterpret_cast<const float4*>(g_pool2 + bb * 16000 + k0 + 4 * kq);
    }
    #pragma unroll
    for (int j = 0; j < 4; j++) {
        int i4 = t + j * 256;
        int oc = i4 >> 3, kq = i4 & 7;
        Ws[4 * kq + 0][oc] = rw[j].x;
        Ws[4 * kq + 1][oc] = rw[j].y;
        Ws[4 * kq + 2][oc] = rw[j].z;
        Ws[4 * kq + 3][oc] = rw[j].w;
    }
    #pragma unroll
    for (int j = 0; j < 2; j++) {
        int i4 = t + j * 256;
        int bb = i4 >> 3, kq = i4 & 7;
        Xs[4 * kq + 0][bb] = rx[j].x;
        Xs[4 * kq + 1][bb] = rx[j].y;
        Xs[4 * kq + 2][bb] = rx[j].z;
        Xs[4 * kq + 3][bb] = rx[j].w;
    }
    __syncthreads();

    ull acc[4][4];
    #pragma unroll
    for (int o = 0; o < 4; o++)
        #pragma unroll
        for (int j = 0; j < 4; j++) acc[o][j] = 0ull;

    #pragma unroll 8
    for (int kk = 0; kk < 32; kk++) {
        const ull* xq = reinterpret_cast<const ull*>(&Xs[kk][8 * bg]);
        ull x0 = xq[0], x1 = xq[1], x2 = xq[2], x3 = xq[3];
        #pragma unroll
        for (int o = 0; o < 4; o++) {
            float wv = Ws[kk][og + 32 * o];
            ull wd = pk2(wv, wv);
            acc[o][0] = fma2(x0, wd, acc[o][0]);
            acc[o][1] = fma2(x1, wd, acc[o][1]);
            acc[o][2] = fma2(x2, wd, acc[o][2]);
            acc[o][3] = fma2(x3, wd, acc[o][3]);
        }
    }

    #pragma unroll
    for (int o = 0; o < 4; o++) {
        int oc = og + 32 * o;
        #pragma unroll
        for (int j = 0; j < 4; j++) {
            float2 v = upk2(acc[o][j]);
            int bb = 8 * bg + 2 * j;
            g_part3[(ks * 64 + bb) * 128 + oc]     = v.x;
            g_part3[(ks * 64 + bb + 1) * 128 + oc] = v.y;
        }
    }
}

// ---------------------------------------------------------------------------
// K_red: stage-1 partial reduction, FLOAT4. grid (32 s, 64 b) = 2048 blocks,
// 128 threads. Thread (q, j): oc quad 4q, sums ks = s+32j+128i (i=0..3, only
// i=3 needs a bound guard since s+32j <= 127). One smem fold over j.
// ---------------------------------------------------------------------------
__global__ void __launch_bounds__(128) k_red() {
    int s = blockIdx.x;         // 0..31
    int b = blockIdx.y;         // 0..63
    int t = threadIdx.x;
    int q = t & 31, j = t >> 5; // oc quad, ks sub
    __shared__ __align__(16) float4 red[4][32];

    const float* base = g_part3 + (size_t)b * 128 + 4 * q;
    int k0 = s + 32 * j;        // <= 127
    float4 v0 = *reinterpret_cast<const float4*>(base + (size_t)(k0)       * 8192);
    float4 v1 = *reinterpret_cast<const float4*>(base + (size_t)(k0 + 128) * 8192);
    float4 v2 = *reinterpret_cast<const float4*>(base + (size_t)(k0 + 256) * 8192);
    float4 v3 = make_float4(0.f, 0.f, 0.f, 0.f);
    if (k0 + 384 < 500)
        v3 = *reinterpret_cast<const float4*>(base + (size_t)(k0 + 384) * 8192);
    float4 a = make_float4((v0.x + v1.x) + (v2.x + v3.x),
                           (v0.y + v1.y) + (v2.y + v3.y),
                           (v0.z + v1.z) + (v2.z + v3.z),
                           (v0.w + v1.w) + (v2.w + v3.w));
    red[j][q] = a;
    __syncthreads();
    if (t < 32) {
        float4 r0 = red[0][t], r1 = red[1][t], r2 = red[2][t], r3 = red[3][t];
        float4 sum = make_float4((r0.x + r1.x) + (r2.x + r3.x),
                                 (r0.y + r1.y) + (r2.y + r3.y),
                                 (r0.z + r1.z) + (r2.z + r3.z),
                                 (r0.w + r1.w) + (r2.w + r3.w));
        *reinterpret_cast<float4*>(g_red + ((size_t)s * 64 + b) * 128 + 4 * t) = sum;
    }
}

// ---------------------------------------------------------------------------
// K6: final reduce (+bc3), FC 128->64 (+bn relu), FC 64->12, log_softmax.
// one block per batch, 128 threads; 32 L2-hot partial loads per thread.
// ---------------------------------------------------------------------------
__global__ void __launch_bounds__(128) k_fc(
        const float* __restrict__ bc3, const float* __restrict__ Wf,
        const float* __restrict__ bf, const float* __restrict__ gf,
        const float* __restrict__ bef, const float* __restrict__ Wo,
        const float* __restrict__ bo, float* __restrict__ out) {
    int b = blockIdx.x;
    int t = threadIdx.x;
    __shared__ float f[128], u[64], o[12];
    {
        const float* p = g_red + b * 128 + t;
        float a0 = 0.f, a1 = 0.f, a2 = 0.f, a3 = 0.f;
        #pragma unroll
        for (int s = 0; s < 32; s += 4) {
            a0 += p[(s + 0) * 8192];
            a1 += p[(s + 1) * 8192];
            a2 += p[(s + 2) * 8192];
            a3 += p[(s + 3) * 8192];
        }
        f[t] = bc3[t] + ((a0 + a1) + (a2 + a3));
    }
    __syncthreads();
    if (t < 64) {
        float z = bf[t];
        #pragma unroll 8
        for (int k = 0; k < 128; k++) z = fmaf(f[k], Wf[k * 64 + t], z);
        z = z * (INV_BN * gf[t]) + bef[t];
        u[t] = fmaxf(z, 0.f);
    }
    __syncthreads();
    if (t < 12) {
        float z = bo[t];
        #pragma unroll 8
        for (int k = 0; k < 64; k++) z = fmaf(u[k], Wo[k * 12 + t], z);
        o[t] = z;
    }
    __syncthreads();
    if (t < 12) {
        float m = o[0];
        #pragma unroll
        for (int i = 1; i < 12; i++) m = fmaxf(m, o[i]);
        float s = 0.f;
        #pragma unroll
        for (int i = 0; i < 12; i++) s += expf(o[i] - m);
        out[b * 12 + t] = (o[t] - m) - logf(s);
    }
}

// ---------------------------------------------------------------------------
extern "C" void kernel_launch(void* const* d_in, const int* in_sizes, int n_in,
                              void* d_out, int out_size) {
    const float* x_sample = (const float*)d_in[0];
    const float* x_graph  = (const float*)d_in[1];
    const float* W1   = (const float*)d_in[2];
    const float* b1   = (const float*)d_in[3];
    const float* gl   = (const float*)d_in[4];
    const float* bl   = (const float*)d_in[5];
    const float* Wg   = (const float*)d_in[6];
    const float* bg   = (const float*)d_in[7];
    const float* g1   = (const float*)d_in[8];
    const float* be1  = (const float*)d_in[9];
    const float* Wc1  = (const float*)d_in[10];
    const float* bc1  = (const float*)d_in[11];
    const float* gc1  = (const float*)d_in[12];
    const float* bec1 = (const float*)d_in[13];
    const float* Wc2  = (const float*)d_in[14];
    const float* bc2  = (const float*)d_in[15];
    const float* gc2  = (const float*)d_in[16];
    const float* bec2 = (const float*)d_in[17];
    const float* Wc3  = (const float*)d_in[18];
    const float* bc3  = (const float*)d_in[19];
    const float* Wf   = (const float*)d_in[20];
    const float* bf   = (const float*)d_in[21];
    const float* gf   = (const float*)d_in[22];
    const float* bef  = (const float*)d_in[23];
    const float* Wo   = (const float*)d_in[24];
    const float* bo   = (const float*)d_in[25];
    float* out = (float*)d_out;

    k_front <<<128, 1024>>>(x_sample, W1, b1, gl, bl, x_graph, Wg, bg, g1, be1);
    k_conv12<<<dim3(64, 8, 2), 64>>>(Wc1, bc1, gc1, bec1, Wc2, bc2, gc2, bec2);
    k_conv3 <<<500, 256>>>(Wc3);
    k_red   <<<dim3(32, 64), 128>>>();
    k_fc    <<<64, 128>>>(bc3, Wf, bf, gf, bef, Wo, bo, out);
}